// round 7
// baseline (speedup 1.0000x reference)
#include <cuda_runtime.h>
#include <math.h>
#include <stdint.h>

#define MAX_ROWS  32768
#define HSZ       32768              // hash slots (power of 2)
#define FBLK      912                // flat-kernel blocks (152 SM x 6)
#define MAX_FBLK  2048
#define MAX_BBLK  (MAX_ROWS / 256)
#define MAX_PBLK  64

// ---------------- device scratch (no allocations allowed) ----------------
__device__ int   g_jfirst[MAX_ROWS];   // min j with gt>0 per row (INT_MAX = none)
__device__ int   g_head[HSZ];
__device__ int   g_next[MAX_ROWS];
__device__ float g_csum[MAX_FBLK];     // flat-kernel coarse partials
__device__ int   g_vany[MAX_BBLK];     // build-kernel valid-any flags
__device__ float g_msum[MAX_PBLK];     // probe partials
__device__ int   g_mcnt[MAX_PBLK];
__device__ int   g_done;               // probe completion counter

__device__ __forceinline__ uint32_t hash_x(float x) {
    uint32_t u = __float_as_uint(x) * 2654435761u;
    return (u >> 17) & (HSZ - 1);
}

// ---------------- kernel 0: init (jfirst sentinel + done counter) ---------
__global__ void __launch_bounds__(256) mc_init_kernel(int rows) {
    const int i = blockIdx.x * 256 + threadIdx.x;
    if (i < rows) g_jfirst[i] = 0x7fffffff;
    if (i == 0)   g_done = 0;
}

// ---------------- kernel 1: flat persistent stream over gt ----------------
// Grid-stride over the whole [rows*L] gt array as float4 (4-batched loads).
// Coarse sum -> per-block partial. jfirst -> atomicMin (rare: only gt>0).
// Hash heads reset here (race-free: inserts happen in the NEXT kernel).
__global__ void __launch_bounds__(256, 6) mc_flat_kernel(
    const float* __restrict__ cm,
    const float* __restrict__ gt,
    int L, long long nv)               // nv = total elements / 4
{
    // hash-head reset (inserts are in a later kernel -> no ordering race)
    for (int i = blockIdx.x * 256 + threadIdx.x; i < HSZ; i += gridDim.x * 256)
        g_head[i] = -1;

    const float4* g4 = (const float4*)gt;
    const long long stride = (long long)gridDim.x * 1024;
    float lsum = 0.0f;

    for (long long base = (long long)blockIdx.x * 1024; base < nv; base += stride) {
        const long long i0 = base + threadIdx.x;
        float4 r[4];
        if (base + 1024 <= nv) {
            #pragma unroll
            for (int i = 0; i < 4; i++)
                r[i] = __ldcs(&g4[i0 + (long long)(i * 256)]);
        } else {
            #pragma unroll
            for (int i = 0; i < 4; i++) {
                const long long ii = i0 + (long long)(i * 256);
                r[i] = (ii < nv) ? __ldcs(&g4[ii]) : make_float4(0.f, 0.f, 0.f, 0.f);
            }
        }
        #pragma unroll
        for (int i = 0; i < 4; i++) {
            const float4 g = r[i];
            if (g.x != 0.0f || g.y != 0.0f || g.z != 0.0f || g.w != 0.0f) {
                const long long jg0 = (i0 + (long long)(i * 256)) << 2;
                #pragma unroll
                for (int c = 0; c < 4; c++) {
                    const float gv = (c == 0) ? g.x : (c == 1) ? g.y : (c == 2) ? g.z : g.w;
                    if (gv != 0.0f) {
                        const long long jg = jg0 + c;
                        lsum += gv * __logf(cm[jg] + 1e-6f);
                        if (gv > 0.0f) {
                            const int row = (int)(jg / (long long)L);
                            const int j   = (int)(jg - (long long)row * L);
                            atomicMin(&g_jfirst[row], j);
                        }
                    }
                }
            }
        }
    }

    // block reduce lsum -> slot
    #pragma unroll
    for (int o = 16; o > 0; o >>= 1)
        lsum += __shfl_down_sync(0xffffffffu, lsum, o);
    __shared__ float ws[8];
    const int wid = threadIdx.x >> 5;
    if ((threadIdx.x & 31) == 0) ws[wid] = lsum;
    __syncthreads();
    if (threadIdx.x == 0) {
        lsum = 0.0f;
        #pragma unroll
        for (int i = 0; i < 8; i++) lsum += ws[i];
        g_csum[blockIdx.x] = lsum;
    }
}

// ---------------- kernel 2: hash build ------------------------------------
__global__ void __launch_bounds__(256) mc_build_kernel(
    const float* __restrict__ samples0, int rows)
{
    const int tid = threadIdx.x;
    const int r = blockIdx.x * 256 + tid;

    int va = 0;
    if (r < rows) {
        va = (g_jfirst[r] != 0x7fffffff);
        if (va) {
            const float x = ((const float2*)samples0)[r].x;
            g_next[r] = atomicExch(&g_head[hash_x(x)], r);
        }
    }
    #pragma unroll
    for (int o = 16; o > 0; o >>= 1)
        va |= __shfl_down_sync(0xffffffffu, va, o);
    __shared__ int wva[8];
    const int wid = tid >> 5;
    if ((tid & 31) == 0) wva[wid] = va;
    __syncthreads();
    if (tid == 0) {
        va = 0;
        #pragma unroll
        for (int i = 0; i < 8; i++) va |= wva[i];
        g_vany[blockIdx.x] = va;
    }
}

// ---------------- kernel 3: probe + last-block finalize --------------------
__global__ void __launch_bounds__(256) mc_probefin_kernel(
    const float* __restrict__ samples0,
    const float* __restrict__ samples1,
    const float* __restrict__ mkpts0,
    const float* __restrict__ mkpts1,
    float* __restrict__ out,
    int L, int N, int nflat, int nb, int pb, float Bf)
{
    const int tid = threadIdx.x;
    const int n = blockIdx.x * 256 + tid;

    float fs = 0.0f;
    int   fc = 0;
    if (n < N) {
        const float bf = mkpts0[3 * n + 0];
        const float x  = mkpts0[3 * n + 1];
        const float y  = mkpts0[3 * n + 2];
        const float2* s0 = (const float2*)samples0;

        int best = 0x7fffffff;
        for (int r = g_head[hash_x(x)]; r >= 0; r = g_next[r]) {
            const float2 p = s0[r];
            if (p.x == x && p.y == y && (float)(r / L) == bf)
                best = min(best, r);
        }
        if (best != 0x7fffffff) {
            const int jf = g_jfirst[best];
            const int b  = best / L;
            const float2 q = ((const float2*)samples1)[(long long)b * L + jf];
            const float dx = q.x - mkpts1[2 * n + 0];
            const float dy = q.y - mkpts1[2 * n + 1];
            const float nrm = sqrtf(dx * dx + dy * dy);
            if (nrm < 10.0f) { fs = nrm; fc = 1; }
        }
    }

    #pragma unroll
    for (int o = 16; o > 0; o >>= 1) {
        fs += __shfl_down_sync(0xffffffffu, fs, o);
        fc += __shfl_down_sync(0xffffffffu, fc, o);
    }
    __shared__ float wfs[8];
    __shared__ int   wfc[8];
    const int wid = tid >> 5;
    if ((tid & 31) == 0) { wfs[wid] = fs; wfc[wid] = fc; }
    __syncthreads();

    __shared__ int amLast;
    if (tid == 0) {
        fs = 0.0f; fc = 0;
        #pragma unroll
        for (int i = 0; i < 8; i++) { fs += wfs[i]; fc += wfc[i]; }
        g_msum[blockIdx.x] = fs;
        g_mcnt[blockIdx.x] = fc;
        __threadfence();
        amLast = (atomicAdd(&g_done, 1) == pb - 1);
    }
    __syncthreads();

    if (amLast) {
        float cs = 0.0f; fs = 0.0f;
        int   va = 0;    fc = 0;
        for (int i = tid; i < nflat; i += 256) cs += g_csum[i];
        for (int i = tid; i < nb;    i += 256) va |= g_vany[i];
        for (int i = tid; i < pb;    i += 256) { fs += g_msum[i]; fc += g_mcnt[i]; }
        #pragma unroll
        for (int o = 16; o > 0; o >>= 1) {
            cs += __shfl_down_sync(0xffffffffu, cs, o);
            fs += __shfl_down_sync(0xffffffffu, fs, o);
            fc += __shfl_down_sync(0xffffffffu, fc, o);
            va |= __shfl_down_sync(0xffffffffu, va, o);
        }
        __shared__ float wcs2[8], wfs2[8];
        __shared__ int   wfc2[8], wva2[8];
        if ((tid & 31) == 0) { wcs2[wid] = cs; wfs2[wid] = fs; wfc2[wid] = fc; wva2[wid] = va; }
        __syncthreads();
        if (tid == 0) {
            cs = 0.0f; fs = 0.0f; fc = 0; va = 0;
            #pragma unroll
            for (int i = 0; i < 8; i++) {
                cs += wcs2[i]; fs += wfs2[i]; fc += wfc2[i]; va |= wva2[i];
            }
            const float coarse = -cs / Bf;
            float fine;
            if (va) fine = (fc > 0) ? (fs / (float)fc) : 10.0f;
            else    fine = 1e-6f;
            out[0] = coarse + 1000.0f * fine;
            out[1] = coarse;
            out[2] = fine;
        }
    }
}

extern "C" void kernel_launch(void* const* d_in, const int* in_sizes, int n_in,
                              void* d_out, int out_size)
{
    const float* cm       = (const float*)d_in[0];  // [B,L,L]
    const float* gt       = (const float*)d_in[1];  // [B,L,L]
    const float* samples0 = (const float*)d_in[2];  // [B,L,2]
    const float* samples1 = (const float*)d_in[3];  // [B,L,2]
    const float* mkpts0   = (const float*)d_in[4];  // [N,3]
    const float* mkpts1   = (const float*)d_in[5];  // [N,2]
    float* out = (float*)d_out;

    const long long BL = (long long)in_sizes[2] / 2;       // B*L
    const int L = (int)((long long)in_sizes[0] / BL);      // B*L*L / (B*L)
    const int B = (int)(BL / L);
    const int N = in_sizes[4] / 3;
    const int rows = B * L;
    const long long nv = ((long long)in_sizes[0] + 3) / 4; // total gt elems / 4
    const int nb = (rows + 255) / 256;
    const int pb = (N + 255) / 256;

    mc_init_kernel<<<nb, 256>>>(rows);
    mc_flat_kernel<<<FBLK, 256>>>(cm, gt, L, nv);
    mc_build_kernel<<<nb, 256>>>(samples0, rows);
    mc_probefin_kernel<<<pb, 256>>>(samples0, samples1, mkpts0, mkpts1,
                                    out, L, N, FBLK, nb, pb, (float)B);
}

// round 9
// speedup vs baseline: 1.0452x; 1.0452x over previous
#include <cuda_runtime.h>
#include <math.h>
#include <stdint.h>

#define MAX_ROWS    32768
#define HSZ         32768                 // hash table slots (power of 2)
#define MAX_BBLK    (MAX_ROWS / 256)      // build-kernel blocks
#define MAX_PBLK    64                    // probe-kernel blocks

// ---------------- device scratch (no allocations allowed) ----------------
// Fully overwritten each launch in dependency order:
//   row kernel:   g_rowsum, g_jfirst, resets g_head
//   build kernel: g_next, g_head (inserts), g_csum, g_vany, resets g_done
//   probe kernel: g_msum, g_mcnt, increments g_done
__device__ float g_rowsum[MAX_ROWS];
__device__ int   g_jfirst[MAX_ROWS];
__device__ int   g_head[HSZ];
__device__ int   g_next[MAX_ROWS];
__device__ float g_csum[MAX_BBLK];
__device__ int   g_vany[MAX_BBLK];
__device__ float g_msum[MAX_PBLK];
__device__ int   g_mcnt[MAX_PBLK];
__device__ int   g_done;

__device__ __forceinline__ uint32_t hash_x(float x) {
    uint32_t u = __float_as_uint(x) * 2654435761u;
    return (u >> 17) & (HSZ - 1);         // top 15 bits
}

// ---------------- kernel 1: one block (128 thr) per row of [B*L, L] -------
// PROVEN 45.9us variant (R2/R3): streams gt (__ldcs), gathers cm only where
// gt != 0, records first j with gt>0, resets hash heads.
__global__ void __launch_bounds__(128) mc_row_kernel(
    const float* __restrict__ cm,
    const float* __restrict__ gt,
    int L)
{
    // interleaved hash-head reset (covered by the first HSZ/128 blocks)
    for (int i = blockIdx.x * 128 + threadIdx.x; i < HSZ; i += gridDim.x * 128)
        g_head[i] = -1;

    const int row = blockIdx.x;
    const long long base = (long long)row * (long long)L;
    const float*  gr = gt + base;
    const float*  cr = cm + base;
    const float4* g4 = (const float4*)gr;
    const int nv = L >> 2;

    float lsum = 0.0f;
    int   lmin = 0x7fffffff;

    // chunks of 1024 float4s: 8 streaming loads/thread, front-batched (MLP=8)
    int v0 = 0;
    for (; v0 + 1024 <= nv; v0 += 1024) {
        float4 r[8];
        #pragma unroll
        for (int i = 0; i < 8; i++)
            r[i] = __ldcs(&g4[v0 + threadIdx.x + i * 128]);
        #pragma unroll
        for (int i = 0; i < 8; i++) {
            const float4 g = r[i];
            if (g.x != 0.0f || g.y != 0.0f || g.z != 0.0f || g.w != 0.0f) {
                const int j = (v0 + threadIdx.x + i * 128) << 2;
                if (g.x != 0.0f) lsum += g.x * __logf(cr[j + 0] + 1e-6f);
                if (g.y != 0.0f) lsum += g.y * __logf(cr[j + 1] + 1e-6f);
                if (g.z != 0.0f) lsum += g.z * __logf(cr[j + 2] + 1e-6f);
                if (g.w != 0.0f) lsum += g.w * __logf(cr[j + 3] + 1e-6f);
                if      (g.x > 0.0f) lmin = min(lmin, j + 0);
                else if (g.y > 0.0f) lmin = min(lmin, j + 1);
                else if (g.z > 0.0f) lmin = min(lmin, j + 2);
                else if (g.w > 0.0f) lmin = min(lmin, j + 3);
            }
        }
    }
    // remainder float4s
    for (int v = v0 + threadIdx.x; v < nv; v += 128) {
        const float4 g = __ldcs(&g4[v]);
        if (g.x != 0.0f || g.y != 0.0f || g.z != 0.0f || g.w != 0.0f) {
            const int j = v << 2;
            if (g.x != 0.0f) lsum += g.x * __logf(cr[j + 0] + 1e-6f);
            if (g.y != 0.0f) lsum += g.y * __logf(cr[j + 1] + 1e-6f);
            if (g.z != 0.0f) lsum += g.z * __logf(cr[j + 2] + 1e-6f);
            if (g.w != 0.0f) lsum += g.w * __logf(cr[j + 3] + 1e-6f);
            if      (g.x > 0.0f) lmin = min(lmin, j + 0);
            else if (g.y > 0.0f) lmin = min(lmin, j + 1);
            else if (g.z > 0.0f) lmin = min(lmin, j + 2);
            else if (g.w > 0.0f) lmin = min(lmin, j + 3);
        }
    }
    // scalar tail
    for (int j = (nv << 2) + threadIdx.x; j < L; j += 128) {
        const float g = gr[j];
        if (g != 0.0f) lsum += g * __logf(cr[j] + 1e-6f);
        if (g > 0.0f)  lmin = min(lmin, j);
    }

    // block reduce (4 warps)
    #pragma unroll
    for (int o = 16; o > 0; o >>= 1) {
        lsum += __shfl_down_sync(0xffffffffu, lsum, o);
        lmin  = min(lmin, __shfl_down_sync(0xffffffffu, lmin, o));
    }
    __shared__ float ws[4];
    __shared__ int   wm[4];
    const int wid = threadIdx.x >> 5;
    if ((threadIdx.x & 31) == 0) { ws[wid] = lsum; wm[wid] = lmin; }
    __syncthreads();
    if (threadIdx.x == 0) {
        lsum = ws[0] + ws[1] + ws[2] + ws[3];
        lmin = min(min(wm[0], wm[1]), min(wm[2], wm[3]));
        g_rowsum[row] = lsum;
        g_jfirst[row] = (lmin < 0x7fffffff) ? lmin : -1;
    }
}

// ---------------- kernel 2: hash build + coarse partial reduce -------------
// One thread per row. Also resets g_done for the probe kernel.
__global__ void __launch_bounds__(256) mc_build_kernel(
    const float* __restrict__ samples0, int rows)
{
    const int tid = threadIdx.x;
    const int r = blockIdx.x * 256 + tid;

    if (blockIdx.x == 0 && tid == 0) g_done = 0;

    float cs = 0.0f;
    int   va = 0;
    if (r < rows) {
        cs = g_rowsum[r];
        const int jf = g_jfirst[r];
        va = (jf >= 0);
        if (va) {
            const float x = ((const float2*)samples0)[r].x;
            g_next[r] = atomicExch(&g_head[hash_x(x)], r);
        }
    }

    #pragma unroll
    for (int o = 16; o > 0; o >>= 1) {
        cs += __shfl_down_sync(0xffffffffu, cs, o);
        va |= __shfl_down_sync(0xffffffffu, va, o);
    }
    __shared__ float wcs[8];
    __shared__ int   wva[8];
    const int wid = tid >> 5;
    if ((tid & 31) == 0) { wcs[wid] = cs; wva[wid] = va; }
    __syncthreads();
    if (tid == 0) {
        cs = 0.0f; va = 0;
        #pragma unroll
        for (int i = 0; i < 8; i++) { cs += wcs[i]; va |= wva[i]; }
        g_csum[blockIdx.x] = cs;
        g_vany[blockIdx.x] = va;
    }
}

// ---------------- kernel 3: probe + last-block finalize --------------------
__global__ void __launch_bounds__(256) mc_probefin_kernel(
    const float* __restrict__ samples0,
    const float* __restrict__ samples1,
    const float* __restrict__ mkpts0,
    const float* __restrict__ mkpts1,
    float* __restrict__ out,
    int L, int N, int nb, int pb, float Bf)
{
    const int tid = threadIdx.x;
    const int n = blockIdx.x * 256 + tid;

    float fs = 0.0f;
    int   fc = 0;
    if (n < N) {
        const float bf = mkpts0[3 * n + 0];
        const float x  = mkpts0[3 * n + 1];
        const float y  = mkpts0[3 * n + 2];
        const float2* s0 = (const float2*)samples0;

        int best = 0x7fffffff;
        for (int r = g_head[hash_x(x)]; r >= 0; r = g_next[r]) {
            const float2 p = s0[r];
            if (p.x == x && p.y == y && (float)(r / L) == bf)
                best = min(best, r);
        }
        if (best != 0x7fffffff) {
            const int jf = g_jfirst[best];
            const int b  = best / L;
            const float2 q = ((const float2*)samples1)[(long long)b * L + jf];
            const float dx = q.x - mkpts1[2 * n + 0];
            const float dy = q.y - mkpts1[2 * n + 1];
            const float nrm = sqrtf(dx * dx + dy * dy);
            if (nrm < 10.0f) { fs = nrm; fc = 1; }
        }
    }

    #pragma unroll
    for (int o = 16; o > 0; o >>= 1) {
        fs += __shfl_down_sync(0xffffffffu, fs, o);
        fc += __shfl_down_sync(0xffffffffu, fc, o);
    }
    __shared__ float wfs[8];
    __shared__ int   wfc[8];
    const int wid = tid >> 5;
    if ((tid & 31) == 0) { wfs[wid] = fs; wfc[wid] = fc; }
    __syncthreads();

    __shared__ int amLast;
    if (tid == 0) {
        fs = 0.0f; fc = 0;
        #pragma unroll
        for (int i = 0; i < 8; i++) { fs += wfs[i]; fc += wfc[i]; }
        g_msum[blockIdx.x] = fs;
        g_mcnt[blockIdx.x] = fc;
        __threadfence();
        amLast = (atomicAdd(&g_done, 1) == pb - 1);
    }
    __syncthreads();

    if (amLast) {
        float cs = 0.0f; fs = 0.0f;
        int   va = 0;    fc = 0;
        for (int i = tid; i < nb; i += 256) { cs += g_csum[i]; va |= g_vany[i]; }
        for (int i = tid; i < pb; i += 256) { fs += g_msum[i]; fc += g_mcnt[i]; }
        #pragma unroll
        for (int o = 16; o > 0; o >>= 1) {
            cs += __shfl_down_sync(0xffffffffu, cs, o);
            fs += __shfl_down_sync(0xffffffffu, fs, o);
            fc += __shfl_down_sync(0xffffffffu, fc, o);
            va |= __shfl_down_sync(0xffffffffu, va, o);
        }
        __shared__ float wcs2[8], wfs2[8];
        __shared__ int   wfc2[8], wva2[8];
        if ((tid & 31) == 0) { wcs2[wid] = cs; wfs2[wid] = fs; wfc2[wid] = fc; wva2[wid] = va; }
        __syncthreads();
        if (tid == 0) {
            cs = 0.0f; fs = 0.0f; fc = 0; va = 0;
            #pragma unroll
            for (int i = 0; i < 8; i++) {
                cs += wcs2[i]; fs += wfs2[i]; fc += wfc2[i]; va |= wva2[i];
            }
            const float coarse = -cs / Bf;
            float fine;
            if (va) fine = (fc > 0) ? (fs / (float)fc) : 10.0f;
            else    fine = 1e-6f;
            out[0] = coarse + 1000.0f * fine;
            out[1] = coarse;
            out[2] = fine;
        }
    }
}

extern "C" void kernel_launch(void* const* d_in, const int* in_sizes, int n_in,
                              void* d_out, int out_size)
{
    const float* cm       = (const float*)d_in[0];  // [B,L,L]
    const float* gt       = (const float*)d_in[1];  // [B,L,L]
    const float* samples0 = (const float*)d_in[2];  // [B,L,2]
    const float* samples1 = (const float*)d_in[3];  // [B,L,2]
    const float* mkpts0   = (const float*)d_in[4];  // [N,3]
    const float* mkpts1   = (const float*)d_in[5];  // [N,2]
    float* out = (float*)d_out;

    const long long BL = (long long)in_sizes[2] / 2;       // B*L
    const int L = (int)((long long)in_sizes[0] / BL);      // B*L*L / (B*L)
    const int B = (int)(BL / L);
    const int N = in_sizes[4] / 3;
    const int rows = B * L;
    const int nb = (rows + 255) / 256;   // build blocks
    const int pb = (N + 255) / 256;      // probe blocks

    mc_row_kernel<<<rows, 128>>>(cm, gt, L);
    mc_build_kernel<<<nb, 256>>>(samples0, rows);
    mc_probefin_kernel<<<pb, 256>>>(samples0, samples1, mkpts0, mkpts1,
                                    out, L, N, nb, pb, (float)B);
}